// round 3
// baseline (speedup 1.0000x reference)
#include <cuda_runtime.h>
#include <cstddef>

#define T_   512
#define B_   64
#define E_   300
#define H_   512
#define L_   5
#define G3H_ 1536
#define NBLK 128
#define NTHR 256

// ---------------- scratch (no allocations allowed) ----------------
__device__ float g_xp0[(size_t)T_ * B_ * G3H_];   // 201 MB
__device__ float g_xp1[(size_t)T_ * B_ * G3H_];   // 201 MB
__device__ float g_h1 [(size_t)T_ * B_ * H_];     // 67 MB
__device__ float g_h2 [2 * B_ * H_];              // double buffer for layer 1
__device__ float g_pooled[T_ * H_];
__device__ unsigned int g_arrive;

__global__ void init_kernel() { g_arrive = 0u; }

// ---------------- grid-wide barrier (all 128 CTAs co-resident) ----------------
__device__ __forceinline__ void grid_barrier(unsigned int* epoch) {
    __syncthreads();
    if (threadIdx.x == 0) {
        __threadfence();                       // release h writes (membar.gl -> L1 IVALL)
        unsigned int target = (*epoch + 1u) * NBLK;
        atomicAdd(&g_arrive, 1u);
        while (*((volatile unsigned int*)&g_arrive) < target) { }
        __threadfence();                       // acquire: invalidate L1 before new h reads
    }
    __syncthreads();
    ++(*epoch);
}

// ---------------- generic fp32 GEMM: C[M,N] = A[M,K] @ W[N,K]^T + bias[N] ----------------
// Optional row gather on A (embedding lookup fused). 64x64 tile, BK=32, 4x4 per thread.
__global__ void __launch_bounds__(256) gemm_kernel(
    const float* __restrict__ A, const int* __restrict__ gather,
    const float* __restrict__ W, const float* __restrict__ bias,
    float* __restrict__ C, int M, int N, int K)
{
    __shared__ __align__(16) float As[32][68];
    __shared__ __align__(16) float Ws[32][68];

    const int tid = threadIdx.x;
    const int tx = tid & 15;        // 16 cols of 4
    const int ty = tid >> 4;        // 16 rows of 4
    const int m0 = blockIdx.y * 64;
    const int n0 = blockIdx.x * 64;

    float acc[4][4];
    #pragma unroll
    for (int i = 0; i < 4; ++i)
        #pragma unroll
        for (int j = 0; j < 4; ++j) acc[i][j] = 0.f;

    for (int k0 = 0; k0 < K; k0 += 32) {
        #pragma unroll
        for (int l = 0; l < 8; ++l) {
            int p  = tid + l * 256;
            int i  = p >> 5;
            int kk = p & 31;
            int k  = k0 + kk;
            int arow = m0 + i;
            if (gather) arow = gather[arow];
            As[kk][i] = (k < K) ? A[(size_t)arow * K + k] : 0.f;
            Ws[kk][i] = (k < K) ? W[(size_t)(n0 + i) * K + k] : 0.f;
        }
        __syncthreads();
        #pragma unroll
        for (int kk = 0; kk < 32; ++kk) {
            float4 av = *(const float4*)&As[kk][ty * 4];
            float4 wv = *(const float4*)&Ws[kk][tx * 4];
            float a_[4] = {av.x, av.y, av.z, av.w};
            float w_[4] = {wv.x, wv.y, wv.z, wv.w};
            #pragma unroll
            for (int i = 0; i < 4; ++i)
                #pragma unroll
                for (int j = 0; j < 4; ++j)
                    acc[i][j] = fmaf(a_[i], w_[j], acc[i][j]);
        }
        __syncthreads();
    }

    #pragma unroll
    for (int i = 0; i < 4; ++i) {
        #pragma unroll
        for (int j = 0; j < 4; ++j) {
            int n = n0 + tx * 4 + j;
            C[(size_t)(m0 + ty * 4 + i) * N + n] = acc[i][j] + bias[n];
        }
    }
}

// ---------------- persistent GRU recurrence ----------------
// 128 CTAs x 256 threads. CTA owns 4 hidden units (all 3 gates), keeps its
// Whh slice in smem for the whole sequence. Thread = (batch b, unit jj).
// mode 0: write full history to hbuf[T][B][H] (layer 0)
// mode 1: double-buffered h in hbuf[2][B][H], accumulate batch-mean into pooled
__global__ void __launch_bounds__(256) recur_kernel(
    const float* __restrict__ xp, const float* __restrict__ Whh,
    const float* __restrict__ bhh, float* __restrict__ hbuf,
    float* __restrict__ pooled, int mode)
{
    __shared__ __align__(16) float w_s[3 * 4 * 512];   // [gate][jj][k]
    __shared__ float h_s[64 * 65];                     // h chunk, transposed [kk][b]
    __shared__ float sum_s[4 * 64];

    const int tid = threadIdx.x;
    const int u0  = blockIdx.x * 4;

    for (int p = tid; p < 3 * 4 * 512; p += 256) {
        int g  = p / (4 * 512);
        int r  = p - g * (4 * 512);
        int jj = r >> 9;
        int k  = r & 511;
        w_s[p] = Whh[(size_t)(g * 512 + u0 + jj) * 512 + k];
    }

    const int b  = tid & 63;
    const int jj = tid >> 6;
    const int u  = u0 + jj;
    const float bh0 = bhh[u];
    const float bh1 = bhh[512 + u];
    const float bh2 = bhh[1024 + u];
    const float* w0 = &w_s[(0 * 4 + jj) * 512];
    const float* w1 = &w_s[(1 * 4 + jj) * 512];
    const float* w2 = &w_s[(2 * 4 + jj) * 512];
    __syncthreads();

    unsigned int epoch = 0;

    for (int t = 0; t < T_; ++t) {
        float acc0 = 0.f, acc1 = 0.f, acc2 = 0.f;
        float hprev_u = 0.f;

        if (t > 0) {
            const float* hp = (mode == 0)
                ? hbuf + (size_t)(t - 1) * B_ * H_
                : hbuf + (size_t)((t - 1) & 1) * B_ * H_;

            #pragma unroll 1
            for (int k0 = 0; k0 < 512; k0 += 64) {
                __syncthreads();
                #pragma unroll
                for (int l = 0; l < 16; ++l) {
                    int p  = tid + l * 256;
                    int bl = p >> 6;
                    int kk = p & 63;
                    h_s[kk * 65 + bl] = __ldcg(&hp[(size_t)bl * 512 + k0 + kk]);
                }
                __syncthreads();
                #pragma unroll
                for (int kk = 0; kk < 64; kk += 4) {
                    float h0 = h_s[(kk + 0) * 65 + b];
                    float h1 = h_s[(kk + 1) * 65 + b];
                    float h2 = h_s[(kk + 2) * 65 + b];
                    float h3 = h_s[(kk + 3) * 65 + b];
                    float4 wv0 = *(const float4*)&w0[k0 + kk];
                    float4 wv1 = *(const float4*)&w1[k0 + kk];
                    float4 wv2 = *(const float4*)&w2[k0 + kk];
                    acc0 = fmaf(h0, wv0.x, acc0); acc0 = fmaf(h1, wv0.y, acc0);
                    acc0 = fmaf(h2, wv0.z, acc0); acc0 = fmaf(h3, wv0.w, acc0);
                    acc1 = fmaf(h0, wv1.x, acc1); acc1 = fmaf(h1, wv1.y, acc1);
                    acc1 = fmaf(h2, wv1.z, acc1); acc1 = fmaf(h3, wv1.w, acc1);
                    acc2 = fmaf(h0, wv2.x, acc2); acc2 = fmaf(h1, wv2.y, acc2);
                    acc2 = fmaf(h2, wv2.z, acc2); acc2 = fmaf(h3, wv2.w, acc2);
                }
            }
            hprev_u = __ldcg(&hp[(size_t)b * 512 + u]);
        }

        // gates (PyTorch order r,z,n); xp already contains x@Wih^T + bih
        const float* xpt = xp + ((size_t)t * B_ + b) * G3H_;
        float xr = xpt[u];
        float xz = xpt[512 + u];
        float xn = xpt[1024 + u];
        float r = 1.f / (1.f + __expf(-(xr + acc0 + bh0)));
        float z = 1.f / (1.f + __expf(-(xz + acc1 + bh1)));
        float n = tanhf(xn + r * (acc2 + bh2));
        float hnew = (1.f - z) * n + z * hprev_u;

        float* ho = (mode == 0)
            ? hbuf + (size_t)t * B_ * H_
            : hbuf + (size_t)(t & 1) * B_ * H_;
        ho[(size_t)b * 512 + u] = hnew;

        if (mode == 1) {
            __syncthreads();
            sum_s[jj * 64 + b] = hnew;
            __syncthreads();
            if (tid < 4) {
                float s = 0.f;
                #pragma unroll 8
                for (int q = 0; q < 64; ++q) s += sum_s[tid * 64 + q];
                pooled[t * 512 + u0 + tid] = s * (1.0f / 64.0f);
            }
        }

        if (t < T_ - 1) grid_barrier(&epoch);
    }
}

// ---------------- final FC: out[T,5] = pooled[T,512] @ fcW[5,512]^T + fcb ----------------
__global__ void fc_kernel(const float* __restrict__ pooled, const float* __restrict__ fcW,
                          const float* __restrict__ fcb, float* __restrict__ out)
{
    int t    = blockIdx.x;
    int lane = threadIdx.x;      // 32 threads
    float acc[L_];
    #pragma unroll
    for (int l = 0; l < L_; ++l) acc[l] = 0.f;
    for (int k = lane; k < 512; k += 32) {
        float p = pooled[t * 512 + k];
        #pragma unroll
        for (int l = 0; l < L_; ++l) acc[l] = fmaf(p, fcW[l * 512 + k], acc[l]);
    }
    #pragma unroll
    for (int l = 0; l < L_; ++l) {
        #pragma unroll
        for (int off = 16; off > 0; off >>= 1)
            acc[l] += __shfl_down_sync(0xffffffffu, acc[l], off);
    }
    if (lane == 0) {
        #pragma unroll
        for (int l = 0; l < L_; ++l) out[t * L_ + l] = acc[l] + fcb[l];
    }
}

// ---------------- launch ----------------
extern "C" void kernel_launch(void* const* d_in, const int* in_sizes, int n_in,
                              void* d_out, int out_size)
{
    const int*   texts = (const int*)  d_in[0];
    const float* emb   = (const float*)d_in[1];
    const float* Wih0  = (const float*)d_in[2];
    const float* Whh0  = (const float*)d_in[3];
    const float* bih0  = (const float*)d_in[4];
    const float* bhh0  = (const float*)d_in[5];
    const float* Wih1  = (const float*)d_in[6];
    const float* Whh1  = (const float*)d_in[7];
    const float* bih1  = (const float*)d_in[8];
    const float* bhh1  = (const float*)d_in[9];
    const float* fcW   = (const float*)d_in[10];
    const float* fcb   = (const float*)d_in[11];
    float* out = (float*)d_out;

    float *xp0, *xp1, *h1, *h2, *pooled;
    cudaGetSymbolAddress((void**)&xp0,    g_xp0);
    cudaGetSymbolAddress((void**)&xp1,    g_xp1);
    cudaGetSymbolAddress((void**)&h1,     g_h1);
    cudaGetSymbolAddress((void**)&h2,     g_h2);
    cudaGetSymbolAddress((void**)&pooled, g_pooled);

    const int M = T_ * B_;                  // 32768
    dim3 ggrid(G3H_ / 64, M / 64);          // (24, 512)

    // layer 0 input projection (embedding gather fused): xp0 = emb[texts] @ Wih0^T + bih0
    gemm_kernel<<<ggrid, 256>>>(emb, texts, Wih0, bih0, xp0, M, G3H_, E_);

    // layer 0 recurrence -> full h1 history
    init_kernel<<<1, 1>>>();
    recur_kernel<<<NBLK, NTHR>>>(xp0, Whh0, bhh0, h1, nullptr, 0);

    // layer 1 input projection: xp1 = h1 @ Wih1^T + bih1
    gemm_kernel<<<ggrid, 256>>>(h1, nullptr, Wih1, bih1, xp1, M, G3H_, H_);

    // layer 1 recurrence + batch-mean pooling
    init_kernel<<<1, 1>>>();
    recur_kernel<<<NBLK, NTHR>>>(xp1, Whh1, bhh1, h2, pooled, 1);

    // final projection
    fc_kernel<<<T_, 32>>>(pooled, fcW, fcb, out);
}

// round 5
// speedup vs baseline: 1.9151x; 1.9151x over previous
#include <cuda_runtime.h>
#include <cstddef>
#include <cstdint>

#define T_   512
#define B_   64
#define E_   300
#define H_   512
#define L_   5
#define G3H_ 1536
#define NBLK 128
#define NTHR 256

// ---------------- scratch (no allocations allowed) ----------------
__device__ float g_xp0[(size_t)T_ * B_ * G3H_];   // 201 MB
__device__ float g_xp1[(size_t)T_ * B_ * G3H_];   // 201 MB
__device__ float g_h1 [(size_t)T_ * B_ * H_];     // 67 MB  (layer0 history, [t*B+b][H])
__device__ float g_hT [2 * H_ * B_];              // h double buffer, [buf][k][b]
__device__ float g_pooled[T_ * H_];
__device__ unsigned int g_arrive;

__global__ void init_kernel() { g_arrive = 0u; }

// ---------------- f32x2 helpers (FFMA2 only reachable via PTX) ----------------
__device__ __forceinline__ unsigned long long ffma2(unsigned long long a,
                                                    unsigned long long b,
                                                    unsigned long long c) {
    unsigned long long d;
    asm("fma.rn.f32x2 %0, %1, %2, %3;" : "=l"(d) : "l"(a), "l"(b), "l"(c));
    return d;
}
__device__ __forceinline__ unsigned long long pack2(float lo, float hi) {
    unsigned long long d;
    asm("mov.b64 %0, {%1, %2};" : "=l"(d) : "f"(lo), "f"(hi));
    return d;
}
__device__ __forceinline__ float2 unpack2(unsigned long long v) {
    float2 r;
    asm("mov.b64 {%0, %1}, %2;" : "=f"(r.x), "=f"(r.y) : "l"(v));
    return r;
}
__device__ __forceinline__ uint32_t smem_u32(const void* p) {
    uint32_t a;
    asm("{ .reg .u64 t; cvta.to.shared.u64 t, %1; cvt.u32.u64 %0, t; }" : "=r"(a) : "l"(p));
    return a;
}
__device__ __forceinline__ void cp_async16(uint32_t dst, const void* src) {
    asm volatile("cp.async.cg.shared.global [%0], [%1], 16;" :: "r"(dst), "l"(src));
}

// ---------------- grid-wide barrier (all 128 CTAs co-resident, 1 CTA/SM) ----------------
__device__ __forceinline__ void grid_barrier(unsigned int* epoch) {
    __syncthreads();
    if (threadIdx.x == 0) {
        __threadfence();
        unsigned int target = (*epoch + 1u) * NBLK;
        atomicAdd(&g_arrive, 1u);
        while (*((volatile unsigned int*)&g_arrive) < target) { }
        __threadfence();
    }
    __syncthreads();
    ++(*epoch);
}

// ---------------- fp32 GEMM with f32x2 inner: C[M,N] = A[M,K] @ W[N,K]^T + bias ----------------
__global__ void __launch_bounds__(256) gemm_kernel(
    const float* __restrict__ A, const int* __restrict__ gather,
    const float* __restrict__ W, const float* __restrict__ bias,
    float* __restrict__ C, int M, int N, int K)
{
    __shared__ __align__(16) float As[32][68];
    __shared__ __align__(16) float Ws[32][68];

    const int tid = threadIdx.x;
    const int tx = tid & 15;
    const int ty = tid >> 4;
    const int m0 = blockIdx.y * 64;
    const int n0 = blockIdx.x * 64;

    unsigned long long acc2[2][4];   // [m-pair][n], pairs along m
    #pragma unroll
    for (int i = 0; i < 2; ++i)
        #pragma unroll
        for (int j = 0; j < 4; ++j) acc2[i][j] = 0ull;

    for (int k0 = 0; k0 < K; k0 += 32) {
        #pragma unroll
        for (int l = 0; l < 8; ++l) {
            int p  = tid + l * 256;
            int i  = p >> 5;
            int kk = p & 31;
            int k  = k0 + kk;
            int arow = m0 + i;
            if (gather) arow = gather[arow];
            As[kk][i] = (k < K) ? A[(size_t)arow * K + k] : 0.f;
            Ws[kk][i] = (k < K) ? W[(size_t)(n0 + i) * K + k] : 0.f;
        }
        __syncthreads();
        #pragma unroll
        for (int kk = 0; kk < 32; ++kk) {
            float4 av = *(const float4*)&As[kk][ty * 4];
            float4 wv = *(const float4*)&Ws[kk][tx * 4];
            unsigned long long a01 = pack2(av.x, av.y);
            unsigned long long a23 = pack2(av.z, av.w);
            unsigned long long wd[4];
            wd[0] = pack2(wv.x, wv.x); wd[1] = pack2(wv.y, wv.y);
            wd[2] = pack2(wv.z, wv.z); wd[3] = pack2(wv.w, wv.w);
            #pragma unroll
            for (int j = 0; j < 4; ++j) {
                acc2[0][j] = ffma2(a01, wd[j], acc2[0][j]);
                acc2[1][j] = ffma2(a23, wd[j], acc2[1][j]);
            }
        }
        __syncthreads();
    }

    #pragma unroll
    for (int mp = 0; mp < 2; ++mp) {
        #pragma unroll
        for (int j = 0; j < 4; ++j) {
            float2 v = unpack2(acc2[mp][j]);
            int n = n0 + tx * 4 + j;
            float bb = bias[n];
            C[(size_t)(m0 + ty * 4 + mp * 2 + 0) * N + n] = v.x + bb;
            C[(size_t)(m0 + ty * 4 + mp * 2 + 1) * N + n] = v.y + bb;
        }
    }
}

// ---------------- persistent GRU recurrence (f32x2, cp.async pipelined) ----------------
// 128 CTAs x 256 threads, 1 CTA/SM (132KB dyn smem). CTA owns 4 hidden units = 12 W rows.
// hT global layout: [buf][k][b] so staging is a straight (non-transposing) copy.
// Compute thread: warp=k-split(8 of 64k), lane = mg(16, 4 batches) x ng(2, 6 W-rows).
// f32x2 packs along n (W-row pairs free from smem), h duplicated per FMA group.

#define RS_WT    0
#define RS_HT    (512 * 20 * 4)                    // 40960
#define RS_RED   (RS_HT + 2 * 128 * 64 * 4)        // 40960 + 65536 = 106496
#define RS_XPS   (RS_RED + 32 * 8 * 12 * 8)        // + 24576 = 131072
#define RS_POOL  (RS_XPS + 192 * 16)               // + 3072 = 134144
#define RS_TOTAL (RS_POOL + 1024)                  // 135168

__global__ void __launch_bounds__(256) recur_kernel(
    const float* __restrict__ xp, const float* __restrict__ Whh,
    const float* __restrict__ bhh, float* __restrict__ hT,
    float* __restrict__ hist, float* __restrict__ pooled)
{
    extern __shared__ char smem_raw[];
    float* wt   = (float*)(smem_raw + RS_WT);      // [k][20] (12 rows at pos n<6?n:n+2)
    float* h_ts = (float*)(smem_raw + RS_HT);      // [2][128][64]
    unsigned long long* red = (unsigned long long*)(smem_raw + RS_RED); // [pos32][ks8][12]
    float* xps  = (float*)(smem_raw + RS_XPS);     // [3][64] float4
    float* pool = (float*)(smem_raw + RS_POOL);    // [4][64]

    const int tid = threadIdx.x;
    const int u0  = blockIdx.x * 4;

    // stage W^T into smem: wt[k*20 + pos(n)], n = g*4+jj
    for (int n = 0; n < 12; ++n) {
        int g = n >> 2, jj = n & 3;
        int posn = n + ((n >= 6) ? 2 : 0);
        const float* row = Whh + (size_t)(g * 512 + u0 + jj) * 512;
        for (int k = tid; k < 512; k += 256) wt[k * 20 + posn] = row[k];
    }

    // epilogue-thread ids
    const int b  = tid & 63;
    const int jj = tid >> 6;
    const float bh0 = bhh[u0 + jj];
    const float bh1 = bhh[512 + u0 + jj];
    const float bh2 = bhh[1024 + u0 + jj];

    // compute-phase ids
    const int lane = tid & 31;
    const int warp = tid >> 5;          // ks: k-split
    const int mg   = lane & 15;         // batch group (4 batches)
    const int ng   = lane >> 4;         // n group (6 rows)

    const uint32_t hts_base = smem_u32(h_ts);
    __syncthreads();

    unsigned int epoch = 0;

    for (int t = 0; t < T_; ++t) {
        // stage xp[t] slice for this CTA's 4 units
        if (tid < 192) {
            int bb = tid & 63, g = tid >> 6;
            *(float4*)&xps[(g * 64 + bb) * 4] =
                *(const float4*)(xp + ((size_t)t * 64 + bb) * G3H_ + g * 512 + u0);
        }

        unsigned long long acc[4][3];
        #pragma unroll
        for (int m = 0; m < 4; ++m)
            #pragma unroll
            for (int np = 0; np < 3; ++np) acc[m][np] = 0ull;

        const float* hp = hT + (size_t)((t - 1) & 1) * 512 * 64;

        if (t > 0) {
            // ---- pipelined staging + compute over 4 chunks of 128 k ----
            {   // stage chunk 0
                uint32_t dst = hts_base;
                #pragma unroll
                for (int q = 0; q < 8; ++q) {
                    int idx = tid + q * 256;
                    cp_async16(dst + idx * 16, hp + idx * 4);
                }
                asm volatile("cp.async.commit_group;" ::: "memory");
            }
            #pragma unroll 1
            for (int c = 0; c < 4; ++c) {
                __syncthreads();   // all warps done reading buf[(c+1)&1] from chunk c-1
                if (c < 3) {
                    uint32_t dst = hts_base + ((c + 1) & 1) * 32768;
                    const float* src = hp + (c + 1) * 8192;
                    #pragma unroll
                    for (int q = 0; q < 8; ++q) {
                        int idx = tid + q * 256;
                        cp_async16(dst + idx * 16, src + idx * 4);
                    }
                    asm volatile("cp.async.commit_group;" ::: "memory");
                    asm volatile("cp.async.wait_group 1;" ::: "memory");
                } else {
                    asm volatile("cp.async.wait_group 0;" ::: "memory");
                }
                __syncthreads();   // chunk c fully in smem for all threads

                const float* hb = h_ts + (c & 1) * 8192;
                #pragma unroll
                for (int i = 0; i < 16; ++i) {
                    int kk = warp * 16 + i;            // 0..127 within chunk
                    int k  = c * 128 + kk;             // global k
                    float4 h4 = *(const float4*)&hb[kk * 64 + mg * 4];
                    const float* wrow = &wt[k * 20 + ng * 8];
                    unsigned long long wp0 = *(const unsigned long long*)(wrow + 0);
                    unsigned long long wp1 = *(const unsigned long long*)(wrow + 2);
                    unsigned long long wp2 = *(const unsigned long long*)(wrow + 4);
                    unsigned long long hd;
                    hd = pack2(h4.x, h4.x);
                    acc[0][0] = ffma2(hd, wp0, acc[0][0]);
                    acc[0][1] = ffma2(hd, wp1, acc[0][1]);
                    acc[0][2] = ffma2(hd, wp2, acc[0][2]);
                    hd = pack2(h4.y, h4.y);
                    acc[1][0] = ffma2(hd, wp0, acc[1][0]);
                    acc[1][1] = ffma2(hd, wp1, acc[1][1]);
                    acc[1][2] = ffma2(hd, wp2, acc[1][2]);
                    hd = pack2(h4.z, h4.z);
                    acc[2][0] = ffma2(hd, wp0, acc[2][0]);
                    acc[2][1] = ffma2(hd, wp1, acc[2][1]);
                    acc[2][2] = ffma2(hd, wp2, acc[2][2]);
                    hd = pack2(h4.w, h4.w);
                    acc[3][0] = ffma2(hd, wp0, acc[3][0]);
                    acc[3][1] = ffma2(hd, wp1, acc[3][1]);
                    acc[3][2] = ffma2(hd, wp2, acc[3][2]);
                }
            }
        }

        // ---- cross-ks reduction via smem ----
        __syncthreads();   // also covers xps staging for t==0
        {
            int pos = mg * 2 + ng;
            unsigned long long* rp = &red[(pos * 8 + warp) * 12];
            #pragma unroll
            for (int m = 0; m < 4; ++m)
                #pragma unroll
                for (int np = 0; np < 3; ++np) rp[m * 3 + np] = acc[m][np];
        }
        __syncthreads();

        // ---- epilogue: thread (b, jj) ----
        const float* redf = (const float*)red;
        float gh[3];
        #pragma unroll
        for (int g = 0; g < 3; ++g) {
            int n   = g * 4 + jj;
            int ngE = (n >= 6);
            int idx = n - ngE * 6;
            int npE = idx >> 1, half = idx & 1;
            int posE = (b >> 2) * 2 + ngE;
            int mE   = b & 3;
            int base = ((posE * 8) * 12 + mE * 3 + npE) * 2 + half;
            float s = 0.f;
            #pragma unroll
            for (int ks = 0; ks < 8; ++ks) s += redf[base + ks * 24];
            gh[g] = s;
        }

        float xr = xps[(0 * 64 + b) * 4 + jj];
        float xz = xps[(1 * 64 + b) * 4 + jj];
        float xn = xps[(2 * 64 + b) * 4 + jj];
        float hprev = (t > 0) ? __ldcg(&hp[(u0 + jj) * 64 + b]) : 0.f;

        float r = 1.f / (1.f + __expf(-(xr + gh[0] + bh0)));
        float z = 1.f / (1.f + __expf(-(xz + gh[1] + bh1)));
        float nn = tanhf(xn + r * (gh[2] + bh2));
        float hnew = (1.f - z) * nn + z * hprev;

        hT[(size_t)(t & 1) * 512 * 64 + (u0 + jj) * 64 + b] = hnew;
        if (hist) hist[((size_t)t * 64 + b) * 512 + u0 + jj] = hnew;

        if (pooled) {
            pool[jj * 64 + b] = hnew;
            __syncthreads();
            if (tid < 4) {
                float s = 0.f;
                #pragma unroll 8
                for (int q = 0; q < 64; ++q) s += pool[tid * 64 + q];
                pooled[t * 512 + u0 + tid] = s * (1.0f / 64.0f);
            }
        }

        if (t < T_ - 1) grid_barrier(&epoch);
    }
}

// ---------------- final FC: out[T,5] = pooled[T,512] @ fcW[5,512]^T + fcb ----------------
__global__ void fc_kernel(const float* __restrict__ pooled, const float* __restrict__ fcW,
                          const float* __restrict__ fcb, float* __restrict__ out)
{
    int t    = blockIdx.x;
    int lane = threadIdx.x;
    float acc[L_];
    #pragma unroll
    for (int l = 0; l < L_; ++l) acc[l] = 0.f;
    for (int k = lane; k < 512; k += 32) {
        float p = pooled[t * 512 + k];
        #pragma unroll
        for (int l = 0; l < L_; ++l) acc[l] = fmaf(p, fcW[l * 512 + k], acc[l]);
    }
    #pragma unroll
    for (int l = 0; l < L_; ++l) {
        #pragma unroll
        for (int off = 16; off > 0; off >>= 1)
            acc[l] += __shfl_down_sync(0xffffffffu, acc[l], off);
    }
    if (lane == 0) {
        #pragma unroll
        for (int l = 0; l < L_; ++l) out[t * L_ + l] = acc[l] + fcb[l];
    }
}

// ---------------- launch ----------------
extern "C" void kernel_launch(void* const* d_in, const int* in_sizes, int n_in,
                              void* d_out, int out_size)
{
    const int*   texts = (const int*)  d_in[0];
    const float* emb   = (const float*)d_in[1];
    const float* Wih0  = (const float*)d_in[2];
    const float* Whh0  = (const float*)d_in[3];
    const float* bih0  = (const float*)d_in[4];
    const float* bhh0  = (const float*)d_in[5];
    const float* Wih1  = (const float*)d_in[6];
    const float* Whh1  = (const float*)d_in[7];
    const float* bih1  = (const float*)d_in[8];
    const float* bhh1  = (const float*)d_in[9];
    const float* fcW   = (const float*)d_in[10];
    const float* fcb   = (const float*)d_in[11];
    float* out = (float*)d_out;

    float *xp0, *xp1, *h1, *hT, *pooled;
    cudaGetSymbolAddress((void**)&xp0,    g_xp0);
    cudaGetSymbolAddress((void**)&xp1,    g_xp1);
    cudaGetSymbolAddress((void**)&h1,     g_h1);
    cudaGetSymbolAddress((void**)&hT,     g_hT);
    cudaGetSymbolAddress((void**)&pooled, g_pooled);

    static bool attr_set = false;
    if (!attr_set) {
        cudaFuncSetAttribute(recur_kernel,
                             cudaFuncAttributeMaxDynamicSharedMemorySize, RS_TOTAL);
        attr_set = true;
    }

    const int M = T_ * B_;                  // 32768
    dim3 ggrid(G3H_ / 64, M / 64);          // (24, 512)

    // layer 0 input projection (embedding gather fused)
    gemm_kernel<<<ggrid, 256>>>(emb, texts, Wih0, bih0, xp0, M, G3H_, E_);

    // layer 0 recurrence -> h1 history ([t*B+b][H] for the next GEMM)
    init_kernel<<<1, 1>>>();
    recur_kernel<<<NBLK, NTHR, RS_TOTAL>>>(xp0, Whh0, bhh0, hT, h1, nullptr);

    // layer 1 input projection
    gemm_kernel<<<ggrid, 256>>>(h1, nullptr, Wih1, bih1, xp1, M, G3H_, H_);

    // layer 1 recurrence + batch-mean pooling
    init_kernel<<<1, 1>>>();
    recur_kernel<<<NBLK, NTHR, RS_TOTAL>>>(xp1, Whh1, bhh1, hT, nullptr, pooled);

    // final projection
    fc_kernel<<<T_, 32>>>(pooled, fcW, fcb, out);
}